// round 4
// baseline (speedup 1.0000x reference)
#include <cuda_runtime.h>
#include <math.h>
#include <stdint.h>

#define TT 512
#define NN 256
#define CC 256
#define SS 48
#define LL 97
#define LOG2E 1.4426950408889634f
#define LN2   0.6931471805599453f

#define ROWS 2                      // batch rows per CTA (one per compute warp)
#define CHUNK 16                    // timesteps per ring buffer
#define NBUF 3
#define NCHUNK (TT / CHUNK)         // 32
#define GRID (NN / ROWS)            // 128
#define TILE_FLOATS (ROWS * CC)     // 2KB per timestep
#define BUF_FLOATS (CHUNK * TILE_FLOATS)
#define SMEM_BYTES (NBUF * BUF_FLOATS * 4)  // 98304 B
#define NTHREADS 96                 // 2 compute warps + 1 producer warp

__device__ float g_loss_n[NN];
__device__ int   g_count;           // zero-init; self-resetting per launch

__device__ __forceinline__ uint32_t s2u(const void* p) {
    return (uint32_t)__cvta_generic_to_shared(p);
}
__device__ __forceinline__ float ex2f(float x) {
    float y; asm("ex2.approx.ftz.f32 %0, %1;" : "=f"(y) : "f"(x)); return y;
}
__device__ __forceinline__ float lg2f(float x) {
    float y; asm("lg2.approx.ftz.f32 %0, %1;" : "=f"(y) : "f"(x)); return y;
}

__device__ __forceinline__ void mbar_wait(uint32_t addr, uint32_t parity) {
    asm volatile(
        "{\n"
        ".reg .pred P;\n"
        "WL%=:\n"
        "mbarrier.try_wait.parity.acquire.cta.shared::cta.b64 P, [%0], %1, 0x989680;\n"
        "@P bra WD%=;\n"
        "bra WL%=;\n"
        "WD%=:\n"
        "}\n" :: "r"(addr), "r"(parity) : "memory");
}

__global__ __launch_bounds__(NTHREADS, 1)
void ctc_kernel(const float* __restrict__ logits,
                const int*   __restrict__ labels,
                const int*   __restrict__ pred_sizes,
                const int*   __restrict__ tgt_sizes,
                float*       __restrict__ out)
{
    extern __shared__ float tiles[];
    __shared__ __align__(8) unsigned long long mb_full[NBUF];
    __shared__ __align__(8) unsigned long long mb_empty[NBUF];
    __shared__ float red[3];
    __shared__ int s_last;

    const int tid  = threadIdx.x;
    const int wid  = tid >> 5;
    const int lane = tid & 31;

    if (tid == 0) {
        #pragma unroll
        for (int b = 0; b < NBUF; b++) {
            asm volatile("mbarrier.init.shared.b64 [%0], %1;" :: "r"(s2u(&mb_full[b])),  "r"(1));
            asm volatile("mbarrier.init.shared.b64 [%0], %1;" :: "r"(s2u(&mb_empty[b])), "r"(ROWS));
        }
        asm volatile("fence.proxy.async.shared::cta;" ::: "memory");
    }
    __syncthreads();

    const float* src_base = logits + (size_t)blockIdx.x * ROWS * CC;  // + t*NN*CC

    if (wid == ROWS) {
        // ---------------- producer warp ----------------
        if (lane == 0) {
            #pragma unroll 1
            for (int c = 0; c < NCHUNK; c++) {
                const int b = c % NBUF;
                const int r = c / NBUF;
                if (c >= NBUF) mbar_wait(s2u(&mb_empty[b]), (r - 1) & 1);
                uint32_t f = s2u(&mb_full[b]);
                asm volatile("mbarrier.arrive.expect_tx.shared.b64 _, [%0], %1;"
                             :: "r"(f), "r"(BUF_FLOATS * 4) : "memory");
                #pragma unroll
                for (int j = 0; j < CHUNK; j++) {
                    int t = c * CHUNK + j;
                    uint32_t dst = s2u(&tiles[(b * CHUNK + j) * TILE_FLOATS]);
                    const float* src = src_base + (size_t)t * NN * CC;
                    asm volatile("cp.async.bulk.shared::cluster.global.mbarrier::complete_tx::bytes "
                                 "[%0], [%1], %2, [%3];"
                                 :: "r"(dst), "l"(src), "r"(TILE_FLOATS * 4), "r"(f) : "memory");
                }
            }
        }
    } else {
        // ---------------- compute warps (one batch row each) ----------------
        const int n = blockIdx.x * ROWS + wid;
        const int k = lane;
        int lab_a = (2 * k     < SS) ? labels[n * SS + 2 * k]     : 0;  // state 4k+1
        int lab_b = (2 * k + 1 < SS) ? labels[n * SS + 2 * k + 1] : 0;  // state 4k+3
        int lab_p = (2 * k - 1 >= 0) ? labels[n * SS + 2 * k - 1] : 0;
        const float sk1f = ((lab_a != 0) && (lab_a != lab_p)) ? 1.0f : 0.0f;
        const float sk3f = ((lab_b != 0) && (lab_b != lab_a)) ? 1.0f : 0.0f;
        const int in_len = pred_sizes[n];

        float a0 = 0.0f, a1 = 0.0f, a2 = 0.0f, a3 = 0.0f;
        int   X  = 0;                               // stored = true * 2^(-X)
        float xs = (lane == 0) ? 0.0f : 1.0f;       // 2^(X_prev - X), lane0 -> 0

        #pragma unroll 1
        for (int c = 0; c < NCHUNK; c++) {
            const int b = c % NBUF;
            mbar_wait(s2u(&mb_full[b]), (c / NBUF) & 1);

            #pragma unroll
            for (int j = 0; j < CHUNK; j++) {
                const int t = c * CHUNK + j;
                const float* rp = &tiles[(b * CHUNK + j) * TILE_FLOATS + wid * CC];
                if (t < in_len) {
                    if (t == 0) {
                        if (lane == 0) {
                            a0 = ex2f(rp[0]     * LOG2E);
                            a1 = ex2f(rp[lab_a] * LOG2E);
                        }
                    } else {
                        float p0 = ex2f(rp[0]     * LOG2E);
                        float pa = ex2f(rp[lab_a] * LOG2E);
                        float pc = ex2f(rp[lab_b] * LOG2E);
                        float p3 = __shfl_up_sync(0xffffffffu, a3, 1);
                        float q3 = p3 * xs;                   // neighbor a3, rescaled (0 on lane 0)
                        float t01 = a0 + a1;
                        float t23 = a2 + a3;
                        float n0 = (a0 + q3) * p0;
                        float n1 = fmaf(sk1f, q3, t01) * pa;
                        float n2 = (a1 + a2) * p0;
                        float n3 = fmaf(sk3f, a1, t23) * pc;
                        a0 = n0; a1 = n1; a2 = n2; a3 = n3;
                    }
                    if ((t & 3) == 3) {
                        // per-lane power-of-2 renormalization
                        float mx = fmaxf(fmaxf(a0, a1), fmaxf(a2, a3));
                        int Xp = __shfl_up_sync(0xffffffffu, X, 1);   // neighbor X (pre-update)
                        unsigned u = __float_as_uint(mx);
                        int e = (int)(u >> 23);
                        if (e > 0) {
                            float scale = __uint_as_float((unsigned)(254 - e) << 23);
                            X += e - 127;
                            a0 *= scale; a1 *= scale; a2 *= scale; a3 *= scale;
                        } else if (mx == 0.0f && lane > 0) {
                            X = Xp;                 // adopt neighbor frame while empty
                        }
                        // rebuild cross-lane rescale factor for the next window
                        int Xp2 = __shfl_up_sync(0xffffffffu, X, 1);
                        int d = Xp2 - X;
                        d = max(-126, min(126, d));
                        xs = __uint_as_float((unsigned)(d + 127) << 23);
                        if (lane == 0) xs = 0.0f;
                    }
                }
            }

            if (lane == 0)
                asm volatile("mbarrier.arrive.shared.b64 _, [%0];"
                             :: "r"(s2u(&mb_empty[b])) : "memory");
        }

        // per-row loss: true log2(alpha_l) = lg2(stored) + X_lane
        {
            int tl = tgt_sizes[n];
            int i1 = 2 * tl - 1, i2 = 2 * tl;
            int sel1 = i1 & 3, sl1 = i1 >> 2;
            float x1 = (sel1 == 0) ? a0 : (sel1 == 1) ? a1 : (sel1 == 2) ? a2 : a3;
            x1 = __shfl_sync(0xffffffffu, x1, sl1);
            float X1 = (float)__shfl_sync(0xffffffffu, X, sl1);
            int sel2 = i2 & 3, sl2 = i2 >> 2;
            float x2 = (sel2 == 0) ? a0 : (sel2 == 1) ? a1 : (sel2 == 2) ? a2 : a3;
            x2 = __shfl_sync(0xffffffffu, x2, sl2);
            float X2 = (float)__shfl_sync(0xffffffffu, X, sl2);
            float l1 = lg2f(x1) + X1;    // x==0 -> -inf
            float l2 = lg2f(x2) + X2;
            float m  = fmaxf(l1, l2);
            float dd = fminf(l1, l2) - m;
            float lt = m + lg2f(1.0f + ex2f(dd));   // both -inf -> NaN -> sanitized
            float loss = -LN2 * lt;
            if (!(loss <= 1e29f)) loss = 0.0f;      // inf/NaN -> 0 (zero_infinity)
            if (lane == 0) g_loss_n[n] = loss / (float)tl;
        }
    }

    // fused mean-reduction: last CTA to finish does it
    __syncthreads();
    if (tid == 0) {
        __threadfence();
        int old = atomicAdd(&g_count, 1);
        s_last = (old == (int)gridDim.x - 1) ? 1 : 0;
    }
    __syncthreads();
    if (s_last) {
        __threadfence();
        float v = 0.0f;
        for (int i = tid; i < NN; i += NTHREADS) v += __ldcg(&g_loss_n[i]);
        #pragma unroll
        for (int o = 16; o; o >>= 1) v += __shfl_down_sync(0xffffffffu, v, o);
        if (lane == 0) red[wid] = v;
        __syncthreads();
        if (tid == 0) {
            float m = (red[0] + red[1] + red[2]) / (float)NN;
            if (isnan(m) || isinf(m)) m = 0.0f;
            out[0] = m;
            g_count = 0;   // reset for next graph replay
        }
    }
}

extern "C" void kernel_launch(void* const* d_in, const int* in_sizes, int n_in,
                              void* d_out, int out_size)
{
    const float* logits     = (const float*)d_in[0];
    const int*   labels     = (const int*)  d_in[1];
    const int*   pred_sizes = (const int*)  d_in[2];
    const int*   tgt_sizes  = (const int*)  d_in[3];
    float*       out        = (float*)d_out;

    cudaFuncSetAttribute(ctc_kernel, cudaFuncAttributeMaxDynamicSharedMemorySize, SMEM_BYTES);
    ctc_kernel<<<GRID, NTHREADS, SMEM_BYTES>>>(logits, labels, pred_sizes, tgt_sizes, out);
}